// round 8
// baseline (speedup 1.0000x reference)
#include <cuda_runtime.h>
#include <cuda_bf16.h>
#include <cuda_fp8.h>
#include <math.h>
#include <stdint.h>

#define Bsz 8192
#define Gd  1024
#define Ed  256
#define Kd  2048
#define PNULL 0.1f

// ---------------- scratch (device globals; no allocs allowed) ----------------
__device__ __nv_bfloat16  g_pik  [(size_t)Bsz * Kd];    // 32 MB (unnormalized exp)
__device__ __nv_bfloat16  g_w    [(size_t)Bsz * Kd];    // 32 MB
__device__ unsigned char  g_u8   [(size_t)Bsz * Kd];    // 16 MB fp8 u (decode)
__device__ __nv_bfloat16  g_z    [(size_t)Bsz * Ed];    // 4 MB
__device__ unsigned char  g_imgs8[(size_t)Bsz * Gd];    // 8 MB fp8 images
__device__ unsigned char  g_xa8  [(size_t)Gd * Kd];     // 2 MB fp8 (G,K)
__device__ unsigned char  g_xaT8 [(size_t)Kd * Gd];     // 2 MB fp8 (K,G)
__device__ __nv_bfloat16  g_xb   [(size_t)Ed * Kd];     // (E,K) bf16
__device__ __nv_bfloat16  g_xbT  [(size_t)Kd * Ed];     // (K,E) bf16
__device__ float g_c2a[Kd], g_c2b[Kd], g_sums[Bsz], g_z2[Bsz];

// ---------------- helpers ----------------
__device__ __forceinline__ uint32_t s2u(const void* p) {
    uint32_t a;
    asm("{ .reg .u64 t; cvta.to.shared.u64 t, %1; cvt.u32.u64 %0, t; }" : "=r"(a) : "l"(p));
    return a;
}
#define SWZ(o) ((o) ^ (((o) >> 3) & 0x70))

__device__ __forceinline__ void cp16(uint32_t dst, const void* src) {
    asm volatile("cp.async.cg.shared.global [%0], [%1], 16;" :: "r"(dst), "l"(src));
}
#define CP_COMMIT()   asm volatile("cp.async.commit_group;" ::: "memory")
#define CP_WAIT(n)    asm volatile("cp.async.wait_group %0;" :: "n"(n) : "memory")

#define LDSM4(r, addr)                                                              \
    asm volatile("ldmatrix.sync.aligned.m8n8.x4.shared.b16 {%0,%1,%2,%3}, [%4];"    \
        : "=r"((r)[0]), "=r"((r)[1]), "=r"((r)[2]), "=r"((r)[3]) : "r"(addr))

#define MMA(d, a, b0, b1)                                                           \
    asm volatile("mma.sync.aligned.m16n8k16.row.col.f32.bf16.bf16.f32 "             \
        "{%0,%1,%2,%3}, {%4,%5,%6,%7}, {%8,%9}, {%0,%1,%2,%3};"                     \
        : "+f"((d)[0]), "+f"((d)[1]), "+f"((d)[2]), "+f"((d)[3])                    \
        : "r"((a)[0]), "r"((a)[1]), "r"((a)[2]), "r"((a)[3]), "r"(b0), "r"(b1))

#define MMA8(d, a, b0, b1)                                                          \
    asm volatile("mma.sync.aligned.m16n8k32.row.col.f32.e4m3.e4m3.f32 "             \
        "{%0,%1,%2,%3}, {%4,%5,%6,%7}, {%8,%9}, {%0,%1,%2,%3};"                     \
        : "+f"((d)[0]), "+f"((d)[1]), "+f"((d)[2]), "+f"((d)[3])                    \
        : "r"((a)[0]), "r"((a)[1]), "r"((a)[2]), "r"((a)[3]), "r"(b0), "r"(b1))

// ---------------- mma.sync GEMM, byte-addressed K-major operands ----------------
// Tile D[128 x 128] (MI=2, 2 CTA/SM). 128-byte k-chunk = 4 x (k16 bf16 | k32 fp8).
// EPI 0: e = exp(acc*alpha - c2[n]); out_bf16=e; redout[m] += sum_n e     (pik gen)
//     1: out_bf16 = acc / rowvec[m]                                       (z)
//     2: w = pik[m,n]*exp(acc*alpha - c2[n]); out_bf16=w; redout += sum   (w)
//     3: u = exp(acc*alpha - c2[n] - rowvec[m]); out_fp8=u; redout += sum (u, rowvec=z2)
//     4: d = acc/(PNULL+rowvec[m]) - images[m,n]; redout[m] += d^2/G      (loss)
//     5: t = acc / rowvec[m]; out_bf16=t; redout[m] += t^2/E              (z + z2)
template <int FP8, int EPI>
__global__ void __launch_bounds__(256, 2)
mma_gemm(const void* __restrict__ Av, const void* __restrict__ Bv,
         int kbytes, int lda_b, int ldb_b, int ldc, float alpha,
         __nv_bfloat16* __restrict__ out_bf16, unsigned char* __restrict__ out_fp8,
         const __nv_bfloat16* __restrict__ pik,
         const float* __restrict__ c2vec, const float* __restrict__ rowvec,
         const float* __restrict__ images, float* __restrict__ redout)
{
    extern __shared__ char smem[];
    constexpr uint32_t A_ST = 128 * 128;
    constexpr uint32_t B_OFF = 3 * A_ST;
    const char* A = (const char*)Av;
    const char* Bm = (const char*)Bv;
    const uint32_t sb = s2u(smem);
    const int tid = threadIdx.x, wid = tid >> 5, lane = tid & 31;
    const int m0 = blockIdx.y * 128, n0 = blockIdx.x * 128;
    const int wm = (wid & 3) * 32, wn = (wid >> 2) * 64;

    float acc[2][8][4];
#pragma unroll
    for (int i = 0; i < 2; i++)
#pragma unroll
        for (int j = 0; j < 8; j++)
#pragma unroll
            for (int q = 0; q < 4; q++) acc[i][j][q] = 0.f;

    auto loadA = [&](int c, int st) {
#pragma unroll
        for (int u = 0; u < 4; u++) {
            int unit = tid + u * 256;                      // 128 rows x 8 segs
            int row = unit >> 3, seg = unit & 7;
            cp16(sb + st * A_ST + SWZ((uint32_t)(row * 128 + seg * 16)),
                 A + (size_t)(m0 + row) * lda_b + c * 128 + seg * 16);
        }
    };
    auto loadB = [&](int c, int st) {
#pragma unroll
        for (int u = 0; u < 4; u++) {
            int unit = tid + u * 256;
            int row = unit >> 3, seg = unit & 7;
            cp16(sb + B_OFF + st * 16384 + SWZ((uint32_t)(row * 128 + seg * 16)),
                 Bm + (size_t)(n0 + row) * ldb_b + c * 128 + seg * 16);
        }
    };

    const int nch = kbytes >> 7;
    loadA(0, 0); loadB(0, 0); CP_COMMIT();
    if (nch > 1) { loadA(1, 1); loadB(1, 1); CP_COMMIT(); }

    const int lr = lane & 15, lc = (lane >> 4) * 16;

    for (int c = 0; c < nch; c++) {
        if (c == nch - 1) { CP_WAIT(0); } else { CP_WAIT(1); }
        __syncthreads();
        if (c + 2 < nch) {
            loadA(c + 2, (c + 2) % 3); loadB(c + 2, (c + 2) % 3); CP_COMMIT();
        }
        const int st = c % 3;
        const uint32_t sA = sb + st * A_ST;
        const uint32_t sB = sb + B_OFF + st * 16384;
#pragma unroll
        for (int kk = 0; kk < 4; kk++) {
            const int kb = kk * 32 + lc;
            uint32_t a[2][4], b[4][4];
#pragma unroll
            for (int mi = 0; mi < 2; mi++)
                LDSM4(a[mi], sA + SWZ((uint32_t)((wm + mi * 16 + lr) * 128 + kb)));
#pragma unroll
            for (int pi = 0; pi < 4; pi++)
                LDSM4(b[pi], sB + SWZ((uint32_t)((wn + pi * 16 + lr) * 128 + kb)));
#pragma unroll
            for (int mi = 0; mi < 2; mi++)
#pragma unroll
                for (int ni = 0; ni < 8; ni++) {
                    const int pi = ni >> 1, sel = ni & 1;
                    if (FP8) MMA8(acc[mi][ni], a[mi], b[pi][sel], b[pi][sel + 2]);
                    else     MMA(acc[mi][ni], a[mi], b[pi][sel], b[pi][sel + 2]);
                }
        }
    }

    // ---- epilogue ----
    const int g = lane >> 2, cq = lane & 3;
    constexpr float rscale = (EPI == 4) ? 1.0f / Gd : (EPI == 5) ? 1.0f / Ed : 1.0f;
#pragma unroll
    for (int mi = 0; mi < 2; mi++) {
        const int r0 = m0 + wm + mi * 16 + g;
        const int r1 = r0 + 8;
        float rv0 = 1.f, rv1 = 1.f;
        if (EPI == 1 || EPI == 5) { rv0 = 1.0f / rowvec[r0]; rv1 = 1.0f / rowvec[r1]; }
        if (EPI == 3) { rv0 = rowvec[r0]; rv1 = rowvec[r1]; }
        if (EPI == 4) { rv0 = 1.0f / (PNULL + rowvec[r0]); rv1 = 1.0f / (PNULL + rowvec[r1]); }
        float ls0 = 0.f, ls1 = 0.f;
#pragma unroll
        for (int ni = 0; ni < 8; ni++) {
            const int col = n0 + wn + ni * 8 + cq * 2;
            float v00 = acc[mi][ni][0], v01 = acc[mi][ni][1];
            float v10 = acc[mi][ni][2], v11 = acc[mi][ni][3];
            size_t i0 = (size_t)r0 * ldc + col, i1 = (size_t)r1 * ldc + col;
            if (EPI == 0) {
                float c0 = c2vec[col], c1 = c2vec[col + 1];
                float e00 = expf(v00 * alpha - c0), e01 = expf(v01 * alpha - c1);
                float e10 = expf(v10 * alpha - c0), e11 = expf(v11 * alpha - c1);
                *(__nv_bfloat162*)(out_bf16 + i0) = __floats2bfloat162_rn(e00, e01);
                *(__nv_bfloat162*)(out_bf16 + i1) = __floats2bfloat162_rn(e10, e11);
                ls0 += e00 + e01; ls1 += e10 + e11;
            } else if (EPI == 1) {
                *(__nv_bfloat162*)(out_bf16 + i0) = __floats2bfloat162_rn(v00 * rv0, v01 * rv0);
                *(__nv_bfloat162*)(out_bf16 + i1) = __floats2bfloat162_rn(v10 * rv1, v11 * rv1);
            } else if (EPI == 5) {
                float t00 = v00 * rv0, t01 = v01 * rv0;
                float t10 = v10 * rv1, t11 = v11 * rv1;
                *(__nv_bfloat162*)(out_bf16 + i0) = __floats2bfloat162_rn(t00, t01);
                *(__nv_bfloat162*)(out_bf16 + i1) = __floats2bfloat162_rn(t10, t11);
                ls0 += t00 * t00 + t01 * t01; ls1 += t10 * t10 + t11 * t11;
            } else if (EPI == 2) {
                float c0 = c2vec[col], c1 = c2vec[col + 1];
                __nv_bfloat162 p0 = *(const __nv_bfloat162*)(pik + i0);
                __nv_bfloat162 p1 = *(const __nv_bfloat162*)(pik + i1);
                float w00 = __bfloat162float(p0.x) * expf(v00 * alpha - c0);
                float w01 = __bfloat162float(p0.y) * expf(v01 * alpha - c1);
                float w10 = __bfloat162float(p1.x) * expf(v10 * alpha - c0);
                float w11 = __bfloat162float(p1.y) * expf(v11 * alpha - c1);
                *(__nv_bfloat162*)(out_bf16 + i0) = __floats2bfloat162_rn(w00, w01);
                *(__nv_bfloat162*)(out_bf16 + i1) = __floats2bfloat162_rn(w10, w11);
                ls0 += w00 + w01; ls1 += w10 + w11;
            } else if (EPI == 3) {
                float c0 = c2vec[col], c1 = c2vec[col + 1];
                float u00 = expf(v00 * alpha - c0 - rv0), u01 = expf(v01 * alpha - c1 - rv0);
                float u10 = expf(v10 * alpha - c0 - rv1), u11 = expf(v11 * alpha - c1 - rv1);
                *(uint16_t*)(out_fp8 + i0) =
                    __nv_cvt_float2_to_fp8x2(make_float2(u00, u01), __NV_SATFINITE, __NV_E4M3);
                *(uint16_t*)(out_fp8 + i1) =
                    __nv_cvt_float2_to_fp8x2(make_float2(u10, u11), __NV_SATFINITE, __NV_E4M3);
                ls0 += u00 + u01; ls1 += u10 + u11;
            } else {  // EPI 4
                float d;
                d = v00 * rv0 - images[i0];     ls0 += d * d;
                d = v01 * rv0 - images[i0 + 1]; ls0 += d * d;
                d = v10 * rv1 - images[i1];     ls1 += d * d;
                d = v11 * rv1 - images[i1 + 1]; ls1 += d * d;
            }
        }
        if (EPI != 1) {
            ls0 += __shfl_xor_sync(0xffffffffu, ls0, 1);
            ls0 += __shfl_xor_sync(0xffffffffu, ls0, 2);
            ls1 += __shfl_xor_sync(0xffffffffu, ls1, 1);
            ls1 += __shfl_xor_sync(0xffffffffu, ls1, 2);
            if (cq == 0) {
                atomicAdd(&redout[r0], ls0 * rscale);
                atomicAdd(&redout[r1], ls1 * rscale);
            }
        }
    }
}

// ---------------- small kernels ----------------
__global__ void k_cvt8(const float4* __restrict__ s, uint32_t* __restrict__ d, int n4) {
    int i = blockIdx.x * blockDim.x + threadIdx.x;
    if (i < n4) {
        float4 v = s[i];
        uint32_t lo = __nv_cvt_float2_to_fp8x2(make_float2(v.x, v.y), __NV_SATFINITE, __NV_E4M3);
        uint32_t hi = __nv_cvt_float2_to_fp8x2(make_float2(v.z, v.w), __NV_SATFINITE, __NV_E4M3);
        d[i] = (hi << 16) | (lo & 0xFFFFu);
    }
}
// xa: fp32 (R,C) -> fp8 direct (R,C) AND fp8 transposed (C,R)
__global__ void k_xa8(const float* __restrict__ s, unsigned char* __restrict__ dd,
                      unsigned char* __restrict__ dt, int R, int C) {
    __shared__ float t[32][33];
    int c0 = blockIdx.x * 32, r0 = blockIdx.y * 32;
    int tx = threadIdx.x, ty = threadIdx.y;       // block (32,8)
#pragma unroll
    for (int j = 0; j < 32; j += 8) {
        float v = s[(size_t)(r0 + ty + j) * C + c0 + tx];
        t[ty + j][tx] = v;
        dd[(size_t)(r0 + ty + j) * C + c0 + tx] =
            (unsigned char)__nv_cvt_float_to_fp8(v, __NV_SATFINITE, __NV_E4M3);
    }
    __syncthreads();
#pragma unroll
    for (int j = 0; j < 32; j += 8)
        dt[(size_t)(c0 + ty + j) * R + r0 + tx] =
            (unsigned char)__nv_cvt_float_to_fp8(t[tx][ty + j], __NV_SATFINITE, __NV_E4M3);
}
// xb: fp32 (R,C) -> bf16 direct (R,C) AND bf16 transposed (C,R)
__global__ void k_xbb(const float* __restrict__ s, __nv_bfloat16* __restrict__ dd,
                      __nv_bfloat16* __restrict__ dt, int R, int C) {
    __shared__ float t[32][33];
    int c0 = blockIdx.x * 32, r0 = blockIdx.y * 32;
    int tx = threadIdx.x, ty = threadIdx.y;
#pragma unroll
    for (int j = 0; j < 32; j += 8) {
        float v = s[(size_t)(r0 + ty + j) * C + c0 + tx];
        t[ty + j][tx] = v;
        dd[(size_t)(r0 + ty + j) * C + c0 + tx] = __float2bfloat16(v);
    }
    __syncthreads();
#pragma unroll
    for (int j = 0; j < 32; j += 8)
        dt[(size_t)(c0 + ty + j) * R + r0 + tx] = __float2bfloat16(t[tx][ty + j]);
}
// c2 column squared-means, 2D-parallel with atomics (pre-zeroed output)
__global__ void k_c2p(const float* __restrict__ x, float* __restrict__ out,
                      int rows, int rows_per_blk, float inv) {
    int k = blockIdx.x * blockDim.x + threadIdx.x;
    int r0 = blockIdx.y * rows_per_blk;
    float s = 0.f;
    for (int r = r0; r < r0 + rows_per_blk; r++) {
        float v = x[(size_t)r * Kd + k];
        s += v * v;
    }
    atomicAdd(&out[k], s * inv);
}

// ---------------- host ----------------
extern "C" void kernel_launch(void* const* d_in, const int* in_sizes, int n_in,
                              void* d_out, int out_size) {
    (void)in_sizes; (void)n_in; (void)out_size;
    const float* images = (const float*)d_in[0];
    const float* xa     = (const float*)d_in[1];
    const float* xb     = (const float*)d_in[2];
    float* loss = (float*)d_out;

    float *c2a, *c2b, *sums, *z2;
    __nv_bfloat16 *pik, *wb, *zb, *xbb, *xbT;
    unsigned char *imgs8, *xa8, *xaT8, *u8;
    cudaGetSymbolAddress((void**)&pik,   g_pik);
    cudaGetSymbolAddress((void**)&wb,    g_w);
    cudaGetSymbolAddress((void**)&u8,    g_u8);
    cudaGetSymbolAddress((void**)&zb,    g_z);
    cudaGetSymbolAddress((void**)&imgs8, g_imgs8);
    cudaGetSymbolAddress((void**)&xa8,   g_xa8);
    cudaGetSymbolAddress((void**)&xaT8,  g_xaT8);
    cudaGetSymbolAddress((void**)&xbb,   g_xb);
    cudaGetSymbolAddress((void**)&xbT,   g_xbT);
    cudaGetSymbolAddress((void**)&c2a,   g_c2a);
    cudaGetSymbolAddress((void**)&c2b,   g_c2b);
    cudaGetSymbolAddress((void**)&sums,  g_sums);
    cudaGetSymbolAddress((void**)&z2,    g_z2);

    const int SMEM = 3 * (128 * 128) + 3 * 16384;   // 96 KB
    cudaFuncSetAttribute(mma_gemm<1, 0>, cudaFuncAttributeMaxDynamicSharedMemorySize, SMEM);
    cudaFuncSetAttribute(mma_gemm<0, 1>, cudaFuncAttributeMaxDynamicSharedMemorySize, SMEM);
    cudaFuncSetAttribute(mma_gemm<0, 2>, cudaFuncAttributeMaxDynamicSharedMemorySize, SMEM);
    cudaFuncSetAttribute(mma_gemm<0, 3>, cudaFuncAttributeMaxDynamicSharedMemorySize, SMEM);
    cudaFuncSetAttribute(mma_gemm<1, 4>, cudaFuncAttributeMaxDynamicSharedMemorySize, SMEM);
    cudaFuncSetAttribute(mma_gemm<0, 5>, cudaFuncAttributeMaxDynamicSharedMemorySize, SMEM);

    // one-time conversions
    k_cvt8<<<(Bsz * Gd / 4 + 255) / 256, 256>>>((const float4*)images, (uint32_t*)imgs8, Bsz * Gd / 4);
    k_xa8<<<dim3(Kd / 32, Gd / 32), dim3(32, 8)>>>(xa, xa8, xaT8, Gd, Kd);  // (G,K)+(K,G) fp8
    k_xbb<<<dim3(Kd / 32, Ed / 32), dim3(32, 8)>>>(xb, xbb, xbT, Ed, Kd);   // (E,K)+(K,E) bf16
    cudaMemsetAsync(c2a, 0, Kd * sizeof(float));
    cudaMemsetAsync(c2b, 0, Kd * sizeof(float));
    k_c2p<<<dim3(Kd / 256, 8), 256>>>(xa, c2a, Gd, Gd / 8, 1.0f / Gd);
    k_c2p<<<dim3(Kd / 256, 2), 256>>>(xb, c2b, Ed, Ed / 2, 1.0f / Ed);

    dim3 gK(Kd / 128, Bsz / 128);   // (16,64)
    dim3 gE(Ed / 128, Bsz / 128);   // (2,64)
    dim3 gG(Gd / 128, Bsz / 128);   // (8,64)

    // pik_unnorm = exp(images@xa*2/G - c2a) [fp8], sums = softmax denominators
    cudaMemsetAsync(sums, 0, Bsz * sizeof(float));
    mma_gemm<1, 0><<<gK, 256, SMEM>>>(imgs8, xaT8, Gd, Gd, Gd, Kd, 2.0f / Gd,
                                      pik, nullptr, nullptr, c2a, nullptr, nullptr, sums);
    // z = (pik_unnorm @ xb^T) / sums
    mma_gemm<0, 1><<<gE, 256, SMEM>>>(pik, xbb, Kd * 2, Kd * 2, Kd * 2, Ed, 1.0f,
                                      zb, nullptr, nullptr, nullptr, sums, nullptr, nullptr);
    // 4 EM steps; P_NULL and exp(-z2) row constants cancel in xp = w/sum(w)
    for (int s = 0; s < 4; s++) {
        cudaMemsetAsync(sums, 0, Bsz * sizeof(float));
        // w = pik * exp((z@xb)*2/E - c2b); sums = row sums(w)
        mma_gemm<0, 2><<<gK, 256, SMEM>>>(zb, xbT, Ed * 2, Ed * 2, Ed * 2, Kd, 2.0f / Ed,
                                          wb, nullptr, pik, c2b, nullptr, nullptr, sums);
        if (s < 3) {
            mma_gemm<0, 1><<<gE, 256, SMEM>>>(wb, xbb, Kd * 2, Kd * 2, Kd * 2, Ed, 1.0f,
                                              zb, nullptr, nullptr, nullptr, sums, nullptr, nullptr);
        } else {
            cudaMemsetAsync(z2, 0, Bsz * sizeof(float));
            mma_gemm<0, 5><<<gE, 256, SMEM>>>(wb, xbb, Kd * 2, Kd * 2, Kd * 2, Ed, 1.0f,
                                              zb, nullptr, nullptr, nullptr, sums, nullptr, z2);
        }
    }
    // decode: u = exp((z@xb)*2/E - c2b - z2) -> fp8; sums = row sums(u)
    cudaMemsetAsync(sums, 0, Bsz * sizeof(float));
    mma_gemm<0, 3><<<gK, 256, SMEM>>>(zb, xbT, Ed * 2, Ed * 2, Ed * 2, Kd, 2.0f / Ed,
                                      nullptr, u8, nullptr, c2b, z2, nullptr, sums);
    // loss[b] = mean_g ((u/(0.1+sums)) @ xa^T - images)^2   [fp8 GEMM]
    cudaMemsetAsync(loss, 0, Bsz * sizeof(float));
    mma_gemm<1, 4><<<gG, 256, SMEM>>>(u8, xa8, Kd, Kd, Kd, Gd, 1.0f,
                                      nullptr, nullptr, nullptr, nullptr, sums, images, loss);
}

// round 9
// speedup vs baseline: 1.0871x; 1.0871x over previous
#include <cuda_runtime.h>
#include <cuda_bf16.h>
#include <math.h>
#include <stdint.h>

#define Bsz 8192
#define Gd  1024
#define Ed  256
#define Kd  2048
#define PNULL 0.1f

// ---------------- scratch (device globals; no allocs allowed) ----------------
__device__ __nv_bfloat16  g_pik  [(size_t)Bsz * Kd];    // 32 MB (unnormalized exp)
__device__ __nv_bfloat16  g_w    [(size_t)Bsz * Kd];    // 32 MB
__device__ __nv_bfloat16  g_z    [(size_t)Bsz * Ed];    // 4 MB
__device__ __nv_bfloat16  g_imgs [(size_t)Bsz * Gd];    // 16 MB bf16 images
__device__ __nv_bfloat16  g_xa   [(size_t)Gd * Kd];     // (G,K) bf16
__device__ __nv_bfloat16  g_xaT  [(size_t)Kd * Gd];     // (K,G) bf16
__device__ __nv_bfloat16  g_xb   [(size_t)Ed * Kd];     // (E,K) bf16
__device__ __nv_bfloat16  g_xbT  [(size_t)Kd * Ed];     // (K,E) bf16
// packed zero-init region: c2a | c2b | 6 sum buffers | z2  (one memset)
__device__ float g_redzone[2 * Kd + 7 * Bsz];

// ---------------- helpers ----------------
__device__ __forceinline__ uint32_t s2u(const void* p) {
    uint32_t a;
    asm("{ .reg .u64 t; cvta.to.shared.u64 t, %1; cvt.u32.u64 %0, t; }" : "=r"(a) : "l"(p));
    return a;
}
#define SWZ(o) ((o) ^ (((o) >> 3) & 0x70))

__device__ __forceinline__ void cp16(uint32_t dst, const void* src) {
    asm volatile("cp.async.cg.shared.global [%0], [%1], 16;" :: "r"(dst), "l"(src));
}
#define CP_COMMIT()   asm volatile("cp.async.commit_group;" ::: "memory")
#define CP_WAIT(n)    asm volatile("cp.async.wait_group %0;" :: "n"(n) : "memory")

#define LDSM4(r, addr)                                                              \
    asm volatile("ldmatrix.sync.aligned.m8n8.x4.shared.b16 {%0,%1,%2,%3}, [%4];"    \
        : "=r"((r)[0]), "=r"((r)[1]), "=r"((r)[2]), "=r"((r)[3]) : "r"(addr))

#define MMA(d, a, b0, b1)                                                           \
    asm volatile("mma.sync.aligned.m16n8k16.row.col.f32.bf16.bf16.f32 "             \
        "{%0,%1,%2,%3}, {%4,%5,%6,%7}, {%8,%9}, {%0,%1,%2,%3};"                     \
        : "+f"((d)[0]), "+f"((d)[1]), "+f"((d)[2]), "+f"((d)[3])                    \
        : "r"((a)[0]), "r"((a)[1]), "r"((a)[2]), "r"((a)[3]), "r"(b0), "r"(b1))

// ---------------- mma.sync GEMM, byte-addressed K-major operands ----------------
// Tile D[128 x 128], 256 threads, 2 CTA/SM, 3-stage cp.async pipeline.
// EPI 0: e = exp(acc*alpha - c2[n]); out=e (bf16); redout[m] += sum_n e   (pik gen)
//     1: out = acc / rowvec[m]                                            (z)
//     2: w = pik[m,n]*exp(acc*alpha - c2[n]); out=w; redout += sum        (w)
//     3: u = exp(acc*alpha - c2[n] - rowvec[m]); out=u; redout += sum     (u, rowvec=z2)
//     4: d = acc/(PNULL+rowvec[m]) - images[m,n]; redout[m] += d^2/G      (loss)
//     5: t = acc / rowvec[m]; out=t; redout[m] += t^2/E                   (z + z2)
template <int EPI>
__global__ void __launch_bounds__(256, 2)
mma_gemm(const void* __restrict__ Av, const void* __restrict__ Bv,
         int kbytes, int lda_b, int ldb_b, int ldc, float alpha,
         __nv_bfloat16* __restrict__ out_bf16,
         const __nv_bfloat16* __restrict__ pik,
         const float* __restrict__ c2vec, const float* __restrict__ rowvec,
         const float* __restrict__ images, float* __restrict__ redout)
{
    extern __shared__ char smem[];
    constexpr uint32_t A_ST = 128 * 128;
    constexpr uint32_t B_OFF = 3 * A_ST;
    const char* A = (const char*)Av;
    const char* Bm = (const char*)Bv;
    const uint32_t sb = s2u(smem);
    const int tid = threadIdx.x, wid = tid >> 5, lane = tid & 31;
    const int m0 = blockIdx.y * 128, n0 = blockIdx.x * 128;
    const int wm = (wid & 3) * 32, wn = (wid >> 2) * 64;

    float acc[2][8][4];
#pragma unroll
    for (int i = 0; i < 2; i++)
#pragma unroll
        for (int j = 0; j < 8; j++)
#pragma unroll
            for (int q = 0; q < 4; q++) acc[i][j][q] = 0.f;

    auto loadA = [&](int c, int st) {
#pragma unroll
        for (int u = 0; u < 4; u++) {
            int unit = tid + u * 256;                      // 128 rows x 8 segs
            int row = unit >> 3, seg = unit & 7;
            cp16(sb + st * A_ST + SWZ((uint32_t)(row * 128 + seg * 16)),
                 A + (size_t)(m0 + row) * lda_b + c * 128 + seg * 16);
        }
    };
    auto loadB = [&](int c, int st) {
#pragma unroll
        for (int u = 0; u < 4; u++) {
            int unit = tid + u * 256;
            int row = unit >> 3, seg = unit & 7;
            cp16(sb + B_OFF + st * 16384 + SWZ((uint32_t)(row * 128 + seg * 16)),
                 Bm + (size_t)(n0 + row) * ldb_b + c * 128 + seg * 16);
        }
    };

    const int nch = kbytes >> 7;
    loadA(0, 0); loadB(0, 0); CP_COMMIT();
    if (nch > 1) { loadA(1, 1); loadB(1, 1); CP_COMMIT(); }

    const int lr = lane & 15, lc = (lane >> 4) * 16;

    for (int c = 0; c < nch; c++) {
        if (c == nch - 1) { CP_WAIT(0); } else { CP_WAIT(1); }
        __syncthreads();                   // stage c visible; stage (c+2)%3 compute done
        if (c + 2 < nch) {
            loadA(c + 2, (c + 2) % 3); loadB(c + 2, (c + 2) % 3); CP_COMMIT();
        }
        const int st = c % 3;
        const uint32_t sA = sb + st * A_ST;
        const uint32_t sB = sb + B_OFF + st * 16384;
#pragma unroll
        for (int kk = 0; kk < 4; kk++) {
            const int kb = kk * 32 + lc;
            uint32_t a[2][4], b[4][4];
#pragma unroll
            for (int mi = 0; mi < 2; mi++)
                LDSM4(a[mi], sA + SWZ((uint32_t)((wm + mi * 16 + lr) * 128 + kb)));
#pragma unroll
            for (int pi = 0; pi < 4; pi++)
                LDSM4(b[pi], sB + SWZ((uint32_t)((wn + pi * 16 + lr) * 128 + kb)));
#pragma unroll
            for (int mi = 0; mi < 2; mi++)
#pragma unroll
                for (int ni = 0; ni < 8; ni++) {
                    const int pi = ni >> 1, sel = ni & 1;
                    MMA(acc[mi][ni], a[mi], b[pi][sel], b[pi][sel + 2]);
                }
        }
    }

    // ---- epilogue ----
    const int g = lane >> 2, cq = lane & 3;
    constexpr float rscale = (EPI == 4) ? 1.0f / Gd : (EPI == 5) ? 1.0f / Ed : 1.0f;
#pragma unroll
    for (int mi = 0; mi < 2; mi++) {
        const int r0 = m0 + wm + mi * 16 + g;
        const int r1 = r0 + 8;
        float rv0 = 1.f, rv1 = 1.f;
        if (EPI == 1 || EPI == 5) { rv0 = 1.0f / rowvec[r0]; rv1 = 1.0f / rowvec[r1]; }
        if (EPI == 3) { rv0 = rowvec[r0]; rv1 = rowvec[r1]; }
        if (EPI == 4) { rv0 = 1.0f / (PNULL + rowvec[r0]); rv1 = 1.0f / (PNULL + rowvec[r1]); }
        float ls0 = 0.f, ls1 = 0.f;
#pragma unroll
        for (int ni = 0; ni < 8; ni++) {
            const int col = n0 + wn + ni * 8 + cq * 2;
            float v00 = acc[mi][ni][0], v01 = acc[mi][ni][1];
            float v10 = acc[mi][ni][2], v11 = acc[mi][ni][3];
            size_t i0 = (size_t)r0 * ldc + col, i1 = (size_t)r1 * ldc + col;
            if (EPI == 0) {
                float c0 = c2vec[col], c1 = c2vec[col + 1];
                float e00 = expf(v00 * alpha - c0), e01 = expf(v01 * alpha - c1);
                float e10 = expf(v10 * alpha - c0), e11 = expf(v11 * alpha - c1);
                *(__nv_bfloat162*)(out_bf16 + i0) = __floats2bfloat162_rn(e00, e01);
                *(__nv_bfloat162*)(out_bf16 + i1) = __floats2bfloat162_rn(e10, e11);
                ls0 += e00 + e01; ls1 += e10 + e11;
            } else if (EPI == 1) {
                *(__nv_bfloat162*)(out_bf16 + i0) = __floats2bfloat162_rn(v00 * rv0, v01 * rv0);
                *(__nv_bfloat162*)(out_bf16 + i1) = __floats2bfloat162_rn(v10 * rv1, v11 * rv1);
            } else if (EPI == 5) {
                float t00 = v00 * rv0, t01 = v01 * rv0;
                float t10 = v10 * rv1, t11 = v11 * rv1;
                *(__nv_bfloat162*)(out_bf16 + i0) = __floats2bfloat162_rn(t00, t01);
                *(__nv_bfloat162*)(out_bf16 + i1) = __floats2bfloat162_rn(t10, t11);
                ls0 += t00 * t00 + t01 * t01; ls1 += t10 * t10 + t11 * t11;
            } else if (EPI == 2) {
                float c0 = c2vec[col], c1 = c2vec[col + 1];
                __nv_bfloat162 p0 = *(const __nv_bfloat162*)(pik + i0);
                __nv_bfloat162 p1 = *(const __nv_bfloat162*)(pik + i1);
                float w00 = __bfloat162float(p0.x) * expf(v00 * alpha - c0);
                float w01 = __bfloat162float(p0.y) * expf(v01 * alpha - c1);
                float w10 = __bfloat162float(p1.x) * expf(v10 * alpha - c0);
                float w11 = __bfloat162float(p1.y) * expf(v11 * alpha - c1);
                *(__nv_bfloat162*)(out_bf16 + i0) = __floats2bfloat162_rn(w00, w01);
                *(__nv_bfloat162*)(out_bf16 + i1) = __floats2bfloat162_rn(w10, w11);
                ls0 += w00 + w01; ls1 += w10 + w11;
            } else if (EPI == 3) {
                float c0 = c2vec[col], c1 = c2vec[col + 1];
                float u00 = expf(v00 * alpha - c0 - rv0), u01 = expf(v01 * alpha - c1 - rv0);
                float u10 = expf(v10 * alpha - c0 - rv1), u11 = expf(v11 * alpha - c1 - rv1);
                *(__nv_bfloat162*)(out_bf16 + i0) = __floats2bfloat162_rn(u00, u01);
                *(__nv_bfloat162*)(out_bf16 + i1) = __floats2bfloat162_rn(u10, u11);
                ls0 += u00 + u01; ls1 += u10 + u11;
            } else {  // EPI 4
                float d;
                d = v00 * rv0 - images[i0];     ls0 += d * d;
                d = v01 * rv0 - images[i0 + 1]; ls0 += d * d;
                d = v10 * rv1 - images[i1];     ls1 += d * d;
                d = v11 * rv1 - images[i1 + 1]; ls1 += d * d;
            }
        }
        if (EPI != 1) {
            ls0 += __shfl_xor_sync(0xffffffffu, ls0, 1);
            ls0 += __shfl_xor_sync(0xffffffffu, ls0, 2);
            ls1 += __shfl_xor_sync(0xffffffffu, ls1, 1);
            ls1 += __shfl_xor_sync(0xffffffffu, ls1, 2);
            if (cq == 0) {
                atomicAdd(&redout[r0], ls0 * rscale);
                atomicAdd(&redout[r1], ls1 * rscale);
            }
        }
    }
}

// ---------------- prep kernels ----------------
__global__ void k_cvt4(const float4* __restrict__ s, __nv_bfloat162* __restrict__ d, int n4) {
    int i = blockIdx.x * blockDim.x + threadIdx.x;
    if (i < n4) {
        float4 v = s[i];
        d[2 * i]     = __floats2bfloat162_rn(v.x, v.y);
        d[2 * i + 1] = __floats2bfloat162_rn(v.z, v.w);
    }
}
// fused weight prep: fp32 (R,C) -> bf16 direct (R,C), bf16 transposed (C,R),
// and c2[k] += sum_r x^2 * inv (c2 pre-zeroed)
__global__ void k_prep(const float* __restrict__ s, __nv_bfloat16* __restrict__ dd,
                       __nv_bfloat16* __restrict__ dt, float* __restrict__ c2,
                       int R, int C, float inv) {
    __shared__ float t[32][33];
    int c0 = blockIdx.x * 32, r0 = blockIdx.y * 32;
    int tx = threadIdx.x, ty = threadIdx.y;       // block (32,8)
    float sq = 0.f;
#pragma unroll
    for (int j = 0; j < 32; j += 8) {
        float v = s[(size_t)(r0 + ty + j) * C + c0 + tx];
        t[ty + j][tx] = v;
        dd[(size_t)(r0 + ty + j) * C + c0 + tx] = __float2bfloat16(v);
        sq += v * v;
    }
    atomicAdd(&c2[c0 + tx], sq * inv);
    __syncthreads();
#pragma unroll
    for (int j = 0; j < 32; j += 8)
        dt[(size_t)(c0 + ty + j) * R + r0 + tx] = __float2bfloat16(t[tx][ty + j]);
}

// ---------------- host ----------------
extern "C" void kernel_launch(void* const* d_in, const int* in_sizes, int n_in,
                              void* d_out, int out_size) {
    (void)in_sizes; (void)n_in; (void)out_size;
    const float* images = (const float*)d_in[0];
    const float* xa     = (const float*)d_in[1];
    const float* xb     = (const float*)d_in[2];
    float* loss = (float*)d_out;

    float* rz;
    __nv_bfloat16 *pik, *wb, *zb, *imgs, *xab, *xaT, *xbb, *xbT;
    cudaGetSymbolAddress((void**)&pik,  g_pik);
    cudaGetSymbolAddress((void**)&wb,   g_w);
    cudaGetSymbolAddress((void**)&zb,   g_z);
    cudaGetSymbolAddress((void**)&imgs, g_imgs);
    cudaGetSymbolAddress((void**)&xab,  g_xa);
    cudaGetSymbolAddress((void**)&xaT,  g_xaT);
    cudaGetSymbolAddress((void**)&xbb,  g_xb);
    cudaGetSymbolAddress((void**)&xbT,  g_xbT);
    cudaGetSymbolAddress((void**)&rz,   g_redzone);
    float* c2a = rz;                 // [Kd]
    float* c2b = rz + Kd;            // [Kd]
    float* S0  = rz + 2 * Kd;        // 6 sum buffers + z2, each [Bsz]
    float* S1  = S0 + Bsz;
    float* S2  = S1 + Bsz;
    float* S3  = S2 + Bsz;
    float* S4  = S3 + Bsz;
    float* S5  = S4 + Bsz;
    float* Z2  = S5 + Bsz;

    const int SMEM = 3 * (128 * 128) + 3 * 16384;   // 96 KB
    cudaFuncSetAttribute(mma_gemm<0>, cudaFuncAttributeMaxDynamicSharedMemorySize, SMEM);
    cudaFuncSetAttribute(mma_gemm<1>, cudaFuncAttributeMaxDynamicSharedMemorySize, SMEM);
    cudaFuncSetAttribute(mma_gemm<2>, cudaFuncAttributeMaxDynamicSharedMemorySize, SMEM);
    cudaFuncSetAttribute(mma_gemm<3>, cudaFuncAttributeMaxDynamicSharedMemorySize, SMEM);
    cudaFuncSetAttribute(mma_gemm<4>, cudaFuncAttributeMaxDynamicSharedMemorySize, SMEM);
    cudaFuncSetAttribute(mma_gemm<5>, cudaFuncAttributeMaxDynamicSharedMemorySize, SMEM);

    // zero all reduction buffers + c2 in ONE memset, then prep (atomics into c2)
    cudaMemsetAsync(rz, 0, (2 * Kd + 7 * Bsz) * sizeof(float));
    cudaMemsetAsync(loss, 0, Bsz * sizeof(float));
    k_cvt4<<<(Bsz * Gd / 4 + 255) / 256, 256>>>((const float4*)images,
                                                (__nv_bfloat162*)imgs, Bsz * Gd / 4);
    k_prep<<<dim3(Kd / 32, Gd / 32), dim3(32, 8)>>>(xa, xab, xaT, c2a, Gd, Kd, 1.0f / Gd);
    k_prep<<<dim3(Kd / 32, Ed / 32), dim3(32, 8)>>>(xb, xbb, xbT, c2b, Ed, Kd, 1.0f / Ed);

    dim3 gK(Kd / 128, Bsz / 128);   // (16,64)
    dim3 gE(Ed / 128, Bsz / 128);   // (2,64)
    dim3 gG(Gd / 128, Bsz / 128);   // (8,64)

    // pik_unnorm = exp(images@xa*2/G - c2a); S0 = softmax denominators
    mma_gemm<0><<<gK, 256, SMEM>>>(imgs, xaT, Gd * 2, Gd * 2, Gd * 2, Kd, 2.0f / Gd,
                                   pik, nullptr, c2a, nullptr, nullptr, S0);
    // z = (pik_unnorm @ xb^T) / S0
    mma_gemm<1><<<gE, 256, SMEM>>>(pik, xbb, Kd * 2, Kd * 2, Kd * 2, Ed, 1.0f,
                                   zb, nullptr, nullptr, S0, nullptr, nullptr);
    // 4 EM steps; P_NULL and exp(-z2) row constants cancel in xp = w/sum(w)
    float* Ssum[4] = {S1, S2, S3, S4};
    for (int s = 0; s < 4; s++) {
        // w = pik * exp((z@xb)*2/E - c2b); Ssum[s] = row sums(w)
        mma_gemm<2><<<gK, 256, SMEM>>>(zb, xbT, Ed * 2, Ed * 2, Ed * 2, Kd, 2.0f / Ed,
                                       wb, pik, c2b, nullptr, nullptr, Ssum[s]);
        if (s < 3) {
            mma_gemm<1><<<gE, 256, SMEM>>>(wb, xbb, Kd * 2, Kd * 2, Kd * 2, Ed, 1.0f,
                                           zb, nullptr, nullptr, Ssum[s], nullptr, nullptr);
        } else {
            // last step also accumulates z2 = mean_e z^2 for decode
            mma_gemm<5><<<gE, 256, SMEM>>>(wb, xbb, Kd * 2, Kd * 2, Kd * 2, Ed, 1.0f,
                                           zb, nullptr, nullptr, Ssum[s], nullptr, Z2);
        }
    }
    // decode: u = exp((z@xb)*2/E - c2b - z2); S5 = row sums(u)
    mma_gemm<3><<<gK, 256, SMEM>>>(zb, xbT, Ed * 2, Ed * 2, Ed * 2, Kd, 2.0f / Ed,
                                   wb, nullptr, c2b, Z2, nullptr, S5);
    // loss[b] = mean_g ((u/(0.1+S5)) @ xa^T - images)^2
    mma_gemm<4><<<gG, 256, SMEM>>>(wb, xab, Kd * 2, Kd * 2, Kd * 2, Gd, 1.0f,
                                   nullptr, nullptr, nullptr, S5, images, loss);
}

// round 10
// speedup vs baseline: 1.1297x; 1.0391x over previous
#include <cuda_runtime.h>
#include <cuda_bf16.h>
#include <math.h>
#include <stdint.h>

#define Bsz 8192
#define Gd  1024
#define Ed  256
#define Kd  2048
#define PNULL 0.1f

// ---------------- scratch (device globals; no allocs allowed) ----------------
__device__ __nv_bfloat16  g_pik  [(size_t)Bsz * Kd];    // 32 MB (unnormalized exp)
__device__ __nv_bfloat16  g_w    [(size_t)Bsz * Kd];    // 32 MB
__device__ __nv_bfloat16  g_z    [(size_t)Bsz * Ed];    // 4 MB
__device__ __nv_bfloat16  g_imgs [(size_t)Bsz * Gd];    // 16 MB bf16 images
__device__ __nv_bfloat16  g_xa   [(size_t)Gd * Kd];     // (G,K) bf16
__device__ __nv_bfloat16  g_xaT  [(size_t)Kd * Gd];     // (K,G) bf16
__device__ __nv_bfloat16  g_xb   [(size_t)Ed * Kd];     // (E,K) bf16
__device__ __nv_bfloat16  g_xbT  [(size_t)Kd * Ed];     // (K,E) bf16
// packed zero-init region: c2a | c2b | 6 sum buffers | z2  (one memset)
__device__ float g_redzone[2 * Kd + 7 * Bsz];

// ---------------- helpers ----------------
__device__ __forceinline__ uint32_t s2u(const void* p) {
    uint32_t a;
    asm("{ .reg .u64 t; cvta.to.shared.u64 t, %1; cvt.u32.u64 %0, t; }" : "=r"(a) : "l"(p));
    return a;
}
#define SWZ(o) ((o) ^ (((o) >> 3) & 0x70))

__device__ __forceinline__ void cp16(uint32_t dst, const void* src) {
    asm volatile("cp.async.cg.shared.global [%0], [%1], 16;" :: "r"(dst), "l"(src));
}
#define CP_COMMIT()   asm volatile("cp.async.commit_group;" ::: "memory")
#define CP_WAIT(n)    asm volatile("cp.async.wait_group %0;" :: "n"(n) : "memory")

#define LDSM4(r, addr)                                                              \
    asm volatile("ldmatrix.sync.aligned.m8n8.x4.shared.b16 {%0,%1,%2,%3}, [%4];"    \
        : "=r"((r)[0]), "=r"((r)[1]), "=r"((r)[2]), "=r"((r)[3]) : "r"(addr))

#define MMA(d, a, b0, b1)                                                           \
    asm volatile("mma.sync.aligned.m16n8k16.row.col.f32.bf16.bf16.f32 "             \
        "{%0,%1,%2,%3}, {%4,%5,%6,%7}, {%8,%9}, {%0,%1,%2,%3};"                     \
        : "+f"((d)[0]), "+f"((d)[1]), "+f"((d)[2]), "+f"((d)[3])                    \
        : "r"((a)[0]), "r"((a)[1]), "r"((a)[2]), "r"((a)[3]), "r"(b0), "r"(b1))

// ---------------- mma.sync GEMM, byte-addressed K-major operands ----------------
// Tile D[(MI*64) x 128], 256 threads, 2 CTA/SM, 3-stage cp.async pipeline.
// MI=2: warp tile 32x64 (wide GEMMs). MI=1: warp tile 16x64 (skinny z-GEMMs).
// Swizzle identity (kb < 128): SWZ(row*128 + kb) = row*128 + (kb ^ ((row&7)<<4)),
// and all fragment rows differ by multiples of 16 -> single per-thread key sw.
// EPI 0: e = exp(acc*alpha - c2[n]); out=e (bf16); redout[m] += sum_n e   (pik gen)
//     1: out = acc / rowvec[m]                                            (z)
//     2: w = pik[m,n]*exp(acc*alpha - c2[n]); out=w; redout += sum        (w)
//     3: u = exp(acc*alpha - c2[n] - rowvec[m]); out=u; redout += sum     (u, rowvec=z2)
//     4: d = acc/(PNULL+rowvec[m]) - images[m,n]; redout[m] += d^2/G      (loss)
//     5: t = acc / rowvec[m]; out=t; redout[m] += t^2/E                   (z + z2)
template <int MI, int EPI>
__global__ void __launch_bounds__(256, 2)
mma_gemm(const void* __restrict__ Av, const void* __restrict__ Bv,
         int kbytes, int lda_b, int ldb_b, int ldc, float alpha,
         __nv_bfloat16* __restrict__ out_bf16,
         const __nv_bfloat16* __restrict__ pik,
         const float* __restrict__ c2vec, const float* __restrict__ rowvec,
         const float* __restrict__ images, float* __restrict__ redout)
{
    extern __shared__ char smem[];
    constexpr int MTILE = MI * 64;
    constexpr uint32_t A_ST = MTILE * 128;
    constexpr uint32_t B_OFF = 3 * A_ST;
    const char* A = (const char*)Av;
    const char* Bm = (const char*)Bv;
    const uint32_t sb = s2u(smem);
    const int tid = threadIdx.x, wid = tid >> 5, lane = tid & 31;
    const int m0 = blockIdx.y * MTILE, n0 = blockIdx.x * 128;
    const int wm = (wid & 3) * (MI * 16), wn = (wid >> 2) * 64;

    float acc[MI][8][4];
#pragma unroll
    for (int i = 0; i < MI; i++)
#pragma unroll
        for (int j = 0; j < 8; j++)
#pragma unroll
            for (int q = 0; q < 4; q++) acc[i][j][q] = 0.f;

    auto loadA = [&](int c, int st) {
#pragma unroll
        for (int u = 0; u < MI * 2; u++) {
            int unit = tid + u * 256;                      // MTILE rows x 8 segs
            int row = unit >> 3, seg = unit & 7;
            cp16(sb + st * A_ST + SWZ((uint32_t)(row * 128 + seg * 16)),
                 A + (size_t)(m0 + row) * lda_b + c * 128 + seg * 16);
        }
    };
    auto loadB = [&](int c, int st) {
#pragma unroll
        for (int u = 0; u < 4; u++) {
            int unit = tid + u * 256;                      // 128 rows x 8 segs
            int row = unit >> 3, seg = unit & 7;
            cp16(sb + B_OFF + st * 16384 + SWZ((uint32_t)(row * 128 + seg * 16)),
                 Bm + (size_t)(n0 + row) * ldb_b + c * 128 + seg * 16);
        }
    };

    const int nch = kbytes >> 7;
    loadA(0, 0); loadB(0, 0); CP_COMMIT();
    if (nch > 1) { loadA(1, 1); loadB(1, 1); CP_COMMIT(); }

    // hoisted ldmatrix address components (see swizzle identity above)
    const int lr = lane & 15;
    const uint32_t lcs = (uint32_t)(((lane >> 4) << 4) ^ ((lane & 7) << 4));
    const uint32_t abase = (uint32_t)(wm + lr) * 128;
    const uint32_t bbase = (uint32_t)(wn + lr) * 128;

    for (int c = 0; c < nch; c++) {
        if (c == nch - 1) { CP_WAIT(0); } else { CP_WAIT(1); }
        __syncthreads();                   // stage c visible; stage (c+2)%3 compute done
        if (c + 2 < nch) {
            loadA(c + 2, (c + 2) % 3); loadB(c + 2, (c + 2) % 3); CP_COMMIT();
        }
        const int st = c % 3;
        const uint32_t sAa = sb + st * A_ST + abase;
        const uint32_t sBb = sb + B_OFF + st * 16384 + bbase;
#pragma unroll
        for (int kk = 0; kk < 4; kk++) {
            const uint32_t kbx = ((uint32_t)(kk * 32)) ^ lcs;
            uint32_t a[MI][4], b[4][4];
#pragma unroll
            for (int mi = 0; mi < MI; mi++)
                LDSM4(a[mi], sAa + mi * 2048 + kbx);
#pragma unroll
            for (int pi = 0; pi < 4; pi++)
                LDSM4(b[pi], sBb + pi * 2048 + kbx);
#pragma unroll
            for (int mi = 0; mi < MI; mi++)
#pragma unroll
                for (int ni = 0; ni < 8; ni++) {
                    const int pi = ni >> 1, sel = ni & 1;
                    MMA(acc[mi][ni], a[mi], b[pi][sel], b[pi][sel + 2]);
                }
        }
    }

    // ---- epilogue ----
    const int g = lane >> 2, cq = lane & 3;
    constexpr float rscale = (EPI == 4) ? 1.0f / Gd : (EPI == 5) ? 1.0f / Ed : 1.0f;
#pragma unroll
    for (int mi = 0; mi < MI; mi++) {
        const int r0 = m0 + wm + mi * 16 + g;
        const int r1 = r0 + 8;
        float rv0 = 1.f, rv1 = 1.f;
        if (EPI == 1 || EPI == 5) { rv0 = 1.0f / rowvec[r0]; rv1 = 1.0f / rowvec[r1]; }
        if (EPI == 3) { rv0 = rowvec[r0]; rv1 = rowvec[r1]; }
        if (EPI == 4) { rv0 = 1.0f / (PNULL + rowvec[r0]); rv1 = 1.0f / (PNULL + rowvec[r1]); }
        float ls0 = 0.f, ls1 = 0.f;
#pragma unroll
        for (int ni = 0; ni < 8; ni++) {
            const int col = n0 + wn + ni * 8 + cq * 2;
            float v00 = acc[mi][ni][0], v01 = acc[mi][ni][1];
            float v10 = acc[mi][ni][2], v11 = acc[mi][ni][3];
            size_t i0 = (size_t)r0 * ldc + col, i1 = (size_t)r1 * ldc + col;
            if (EPI == 0) {
                float c0 = c2vec[col], c1 = c2vec[col + 1];
                float e00 = expf(v00 * alpha - c0), e01 = expf(v01 * alpha - c1);
                float e10 = expf(v10 * alpha - c0), e11 = expf(v11 * alpha - c1);
                *(__nv_bfloat162*)(out_bf16 + i0) = __floats2bfloat162_rn(e00, e01);
                *(__nv_bfloat162*)(out_bf16 + i1) = __floats2bfloat162_rn(e10, e11);
                ls0 += e00 + e01; ls1 += e10 + e11;
            } else if (EPI == 1) {
                *(__nv_bfloat162*)(out_bf16 + i0) = __floats2bfloat162_rn(v00 * rv0, v01 * rv0);
                *(__nv_bfloat162*)(out_bf16 + i1) = __floats2bfloat162_rn(v10 * rv1, v11 * rv1);
            } else if (EPI == 5) {
                float t00 = v00 * rv0, t01 = v01 * rv0;
                float t10 = v10 * rv1, t11 = v11 * rv1;
                *(__nv_bfloat162*)(out_bf16 + i0) = __floats2bfloat162_rn(t00, t01);
                *(__nv_bfloat162*)(out_bf16 + i1) = __floats2bfloat162_rn(t10, t11);
                ls0 += t00 * t00 + t01 * t01; ls1 += t10 * t10 + t11 * t11;
            } else if (EPI == 2) {
                float c0 = c2vec[col], c1 = c2vec[col + 1];
                __nv_bfloat162 p0 = *(const __nv_bfloat162*)(pik + i0);
                __nv_bfloat162 p1 = *(const __nv_bfloat162*)(pik + i1);
                float w00 = __bfloat162float(p0.x) * expf(v00 * alpha - c0);
                float w01 = __bfloat162float(p0.y) * expf(v01 * alpha - c1);
                float w10 = __bfloat162float(p1.x) * expf(v10 * alpha - c0);
                float w11 = __bfloat162float(p1.y) * expf(v11 * alpha - c1);
                *(__nv_bfloat162*)(out_bf16 + i0) = __floats2bfloat162_rn(w00, w01);
                *(__nv_bfloat162*)(out_bf16 + i1) = __floats2bfloat162_rn(w10, w11);
                ls0 += w00 + w01; ls1 += w10 + w11;
            } else if (EPI == 3) {
                float c0 = c2vec[col], c1 = c2vec[col + 1];
                float u00 = expf(v00 * alpha - c0 - rv0), u01 = expf(v01 * alpha - c1 - rv0);
                float u10 = expf(v10 * alpha - c0 - rv1), u11 = expf(v11 * alpha - c1 - rv1);
                *(__nv_bfloat162*)(out_bf16 + i0) = __floats2bfloat162_rn(u00, u01);
                *(__nv_bfloat162*)(out_bf16 + i1) = __floats2bfloat162_rn(u10, u11);
                ls0 += u00 + u01; ls1 += u10 + u11;
            } else {  // EPI 4
                float d;
                d = v00 * rv0 - images[i0];     ls0 += d * d;
                d = v01 * rv0 - images[i0 + 1]; ls0 += d * d;
                d = v10 * rv1 - images[i1];     ls1 += d * d;
                d = v11 * rv1 - images[i1 + 1]; ls1 += d * d;
            }
        }
        if (EPI != 1) {
            ls0 += __shfl_xor_sync(0xffffffffu, ls0, 1);
            ls0 += __shfl_xor_sync(0xffffffffu, ls0, 2);
            ls1 += __shfl_xor_sync(0xffffffffu, ls1, 1);
            ls1 += __shfl_xor_sync(0xffffffffu, ls1, 2);
            if (cq == 0) {
                atomicAdd(&redout[r0], ls0 * rscale);
                atomicAdd(&redout[r1], ls1 * rscale);
            }
        }
    }
}

// ---------------- prep kernels ----------------
__global__ void k_cvt4(const float4* __restrict__ s, __nv_bfloat162* __restrict__ d, int n4) {
    int i = blockIdx.x * blockDim.x + threadIdx.x;
    if (i < n4) {
        float4 v = s[i];
        d[2 * i]     = __floats2bfloat162_rn(v.x, v.y);
        d[2 * i + 1] = __floats2bfloat162_rn(v.z, v.w);
    }
}
// fused weight prep: fp32 (R,C) -> bf16 direct (R,C), bf16 transposed (C,R),
// and c2[k] += sum_r x^2 * inv (c2 pre-zeroed)
__global__ void k_prep(const float* __restrict__ s, __nv_bfloat16* __restrict__ dd,
                       __nv_bfloat16* __restrict__ dt, float* __restrict__ c2,
                       int R, int C, float inv) {
    __shared__ float t[32][33];
    int c0 = blockIdx.x * 32, r0 = blockIdx.y * 32;
    int tx = threadIdx.x, ty = threadIdx.y;       // block (32,8)
    float sq = 0.f;
#pragma unroll
    for (int j = 0; j < 32; j += 8) {
        float v = s[(size_t)(r0 + ty + j) * C + c0 + tx];
        t[ty + j][tx] = v;
        dd[(size_t)(r0 + ty + j) * C + c0 + tx] = __float2bfloat16(v);
        sq += v * v;
    }
    atomicAdd(&c2[c0 + tx], sq * inv);
    __syncthreads();
#pragma unroll
    for (int j = 0; j < 32; j += 8)
        dt[(size_t)(c0 + ty + j) * R + r0 + tx] = __float2bfloat16(t[tx][ty + j]);
}

// ---------------- host ----------------
extern "C" void kernel_launch(void* const* d_in, const int* in_sizes, int n_in,
                              void* d_out, int out_size) {
    (void)in_sizes; (void)n_in; (void)out_size;
    const float* images = (const float*)d_in[0];
    const float* xa     = (const float*)d_in[1];
    const float* xb     = (const float*)d_in[2];
    float* loss = (float*)d_out;

    float* rz;
    __nv_bfloat16 *pik, *wb, *zb, *imgs, *xab, *xaT, *xbb, *xbT;
    cudaGetSymbolAddress((void**)&pik,  g_pik);
    cudaGetSymbolAddress((void**)&wb,   g_w);
    cudaGetSymbolAddress((void**)&zb,   g_z);
    cudaGetSymbolAddress((void**)&imgs, g_imgs);
    cudaGetSymbolAddress((void**)&xab,  g_xa);
    cudaGetSymbolAddress((void**)&xaT,  g_xaT);
    cudaGetSymbolAddress((void**)&xbb,  g_xb);
    cudaGetSymbolAddress((void**)&xbT,  g_xbT);
    cudaGetSymbolAddress((void**)&rz,   g_redzone);
    float* c2a = rz;                 // [Kd]
    float* c2b = rz + Kd;            // [Kd]
    float* S0  = rz + 2 * Kd;        // 6 sum buffers + z2, each [Bsz]
    float* S1  = S0 + Bsz;
    float* S2  = S1 + Bsz;
    float* S3  = S2 + Bsz;
    float* S4  = S3 + Bsz;
    float* S5  = S4 + Bsz;
    float* Z2  = S5 + Bsz;

    const int SMEM2 = 3 * (128 * 128) + 3 * 16384;   // 96 KB (MI=2)
    const int SMEM1 = 3 * (64 * 128) + 3 * 16384;    // 72 KB (MI=1)
    cudaFuncSetAttribute(mma_gemm<2, 0>, cudaFuncAttributeMaxDynamicSharedMemorySize, SMEM2);
    cudaFuncSetAttribute(mma_gemm<1, 1>, cudaFuncAttributeMaxDynamicSharedMemorySize, SMEM1);
    cudaFuncSetAttribute(mma_gemm<2, 2>, cudaFuncAttributeMaxDynamicSharedMemorySize, SMEM2);
    cudaFuncSetAttribute(mma_gemm<2, 3>, cudaFuncAttributeMaxDynamicSharedMemorySize, SMEM2);
    cudaFuncSetAttribute(mma_gemm<2, 4>, cudaFuncAttributeMaxDynamicSharedMemorySize, SMEM2);
    cudaFuncSetAttribute(mma_gemm<1, 5>, cudaFuncAttributeMaxDynamicSharedMemorySize, SMEM1);

    // zero all reduction buffers + c2 in ONE memset, then prep (atomics into c2)
    cudaMemsetAsync(rz, 0, (2 * Kd + 7 * Bsz) * sizeof(float));
    cudaMemsetAsync(loss, 0, Bsz * sizeof(float));
    k_cvt4<<<(Bsz * Gd / 4 + 255) / 256, 256>>>((const float4*)images,
                                                (__nv_bfloat162*)imgs, Bsz * Gd / 4);
    k_prep<<<dim3(Kd / 32, Gd / 32), dim3(32, 8)>>>(xa, xab, xaT, c2a, Gd, Kd, 1.0f / Gd);
    k_prep<<<dim3(Kd / 32, Ed / 32), dim3(32, 8)>>>(xb, xbb, xbT, c2b, Ed, Kd, 1.0f / Ed);

    dim3 gK(Kd / 128, Bsz / 128);   // (16,64)  MI=2
    dim3 gE(Ed / 128, Bsz / 64);    // (2,128)  MI=1 -> 256 CTAs, 2 CTA/SM
    dim3 gG(Gd / 128, Bsz / 128);   // (8,64)   MI=2

    // pik_unnorm = exp(images@xa*2/G - c2a); S0 = softmax denominators
    mma_gemm<2, 0><<<gK, 256, SMEM2>>>(imgs, xaT, Gd * 2, Gd * 2, Gd * 2, Kd, 2.0f / Gd,
                                       pik, nullptr, c2a, nullptr, nullptr, S0);
    // z = (pik_unnorm @ xb^T) / S0
    mma_gemm<1, 1><<<gE, 256, SMEM1>>>(pik, xbb, Kd * 2, Kd * 2, Kd * 2, Ed, 1.0f,
                                       zb, nullptr, nullptr, S0, nullptr, nullptr);
    // 4 EM steps; P_NULL and exp(-z2) row constants cancel in xp = w/sum(w)
    float* Ssum[4] = {S1, S2, S3, S4};
    for (int s = 0; s < 4; s++) {
        // w = pik * exp((z@xb)*2/E - c2b); Ssum[s] = row sums(w)
        mma_gemm<2, 2><<<gK, 256, SMEM2>>>(zb, xbT, Ed * 2, Ed * 2, Ed * 2, Kd, 2.0f / Ed,
                                           wb, pik, c2b, nullptr, nullptr, Ssum[s]);
        if (s < 3) {
            mma_gemm<1, 1><<<gE, 256, SMEM1>>>(wb, xbb, Kd * 2, Kd * 2, Kd * 2, Ed, 1.0f,
                                               zb, nullptr, nullptr, Ssum[s], nullptr, nullptr);
        } else {
            // last step also accumulates z2 = mean_e z^2 for decode
            mma_gemm<1, 5><<<gE, 256, SMEM1>>>(wb, xbb, Kd * 2, Kd * 2, Kd * 2, Ed, 1.0f,
                                               zb, nullptr, nullptr, Ssum[s], nullptr, Z2);
        }
    }
    // decode: u = exp((z@xb)*2/E - c2b - z2); S5 = row sums(u)
    mma_gemm<2, 3><<<gK, 256, SMEM2>>>(zb, xbT, Ed * 2, Ed * 2, Ed * 2, Kd, 2.0f / Ed,
                                       wb, nullptr, c2b, Z2, nullptr, S5);
    // loss[b] = mean_g ((u/(0.1+S5)) @ xa^T - images)^2
    mma_gemm<2, 4><<<gG, 256, SMEM2>>>(wb, xab, Kd * 2, Kd * 2, Kd * 2, Gd, 1.0f,
                                       nullptr, nullptr, nullptr, S5, images, loss);
}